// round 2
// baseline (speedup 1.0000x reference)
#include <cuda_runtime.h>
#include <cuda_bf16.h>
#include <cstdint>

#define DEV_INLINE __device__ __forceinline__

constexpr int Bn  = 16;
constexpr int Sn  = 1024;
constexpr int KKn = 512;   // GEMM K = 2 * 256 basis states

// bf16 scratch planes (raw ushort bits).
// AQ row i: [cos(phi_q)(256) | sin(phi_q)(256)]
// BR row j: [cos(phi_k)      | sin(phi_k)     ]  -> re = AQ.BR
// BI row j: [sin(phi_k)      | -cos(phi_k)    ]  -> im = AQ.BI
__device__ __align__(128) unsigned short g_AQ[Bn * Sn * KKn];
__device__ __align__(128) unsigned short g_BR[Bn * Sn * KKn];
__device__ __align__(128) unsigned short g_BI[Bn * Sn * KKn];

DEV_INLINE unsigned short f2bf(float x) {
  __nv_bfloat16 h = __float2bfloat16(x);
  return *reinterpret_cast<unsigned short*>(&h);
}

// ---------- kernel 1: IQP amplitudes ----------
__global__ void iqp_amp_kernel(const float* __restrict__ Q, const float* __restrict__ K) {
  const int tok = blockIdx.x, isK = blockIdx.y;
  const float* X = isK ? K : Q;
  __shared__ float xs[8];
  const int z = threadIdx.x;
  if (z < 8) xs[z] = X[tok * 8 + z];
  __syncthreads();
  float sq = 0.f, L = 0.f;
#pragma unroll
  for (int i = 0; i < 8; ++i) {
    float xi = xs[i];
    sq += xi * xi;
    L  += ((z >> i) & 1) ? -xi : xi;
  }
  const float phase = -0.5f * L - 0.25f * (L * L - sq);
  float s, c;
  sincosf(phase, &s, &c);
  const size_t base = (size_t)tok * KKn;
  if (!isK) {
    g_AQ[base + z]       = f2bf(c);
    g_AQ[base + 256 + z] = f2bf(s);
  } else {
    g_BR[base + z]       = f2bf(c);
    g_BR[base + 256 + z] = f2bf(s);
    g_BI[base + z]       = f2bf(s);
    g_BI[base + 256 + z] = f2bf(-c);
  }
}

// ---------- kernel 2: fused fid-attention ----------
// smem byte offsets
constexpr int SM_A   = 0;        // 8 kc-tiles * [128x64] bf16 = 131072
constexpr int SM_B0R = 131072;   // 16384 each
constexpr int SM_B0I = 147456;
constexpr int SM_B1R = 163840;
constexpr int SM_B1I = 180224;
constexpr int SM_V   = 196608;   // [1024][8] bf16 = 16384
constexpr int SM_CS  = 212992;   // colsum partials [64][8] f32
constexpr int SM_SV  = 215040;   // colsum(V)[8] f32
constexpr int SM_RED = 131072;   // O-reduce, reuses B0R after loop
constexpr int SM_TOTAL = 215072;

DEV_INLINE uint32_t swz(int r, int cchunk) {   // 128B rows, 16B-chunk XOR swizzle
  return (uint32_t)(r * 128 + ((cchunk ^ (r & 7)) << 4));
}
DEV_INLINE void cp16(uint32_t dst, const void* src) {
  asm volatile("cp.async.cg.shared.global [%0], [%1], 16;\n" :: "r"(dst), "l"(src) : "memory");
}
DEV_INLINE void ldsm_x4(uint32_t* r, uint32_t a) {
  asm volatile("ldmatrix.sync.aligned.m8n8.x4.shared.b16 {%0,%1,%2,%3}, [%4];\n"
               : "=r"(r[0]), "=r"(r[1]), "=r"(r[2]), "=r"(r[3]) : "r"(a));
}
DEV_INLINE void ldsm_x2t(uint32_t* r, uint32_t a) {
  asm volatile("ldmatrix.sync.aligned.m8n8.x2.trans.shared.b16 {%0,%1}, [%2];\n"
               : "=r"(r[0]), "=r"(r[1]) : "r"(a));
}
DEV_INLINE void mma16816(float* c, const uint32_t* a, uint32_t b0, uint32_t b1) {
  asm volatile(
      "mma.sync.aligned.m16n8k16.row.col.f32.bf16.bf16.f32 "
      "{%0,%1,%2,%3}, {%4,%5,%6,%7}, {%8,%9}, {%0,%1,%2,%3};\n"
      : "+f"(c[0]), "+f"(c[1]), "+f"(c[2]), "+f"(c[3])
      : "r"(a[0]), "r"(a[1]), "r"(a[2]), "r"(a[3]), "r"(b0), "r"(b1));
}
DEV_INLINE uint32_t pack2(float lo, float hi) {   // -> {hi:lo} bf16x2
  uint32_t r;
  asm("cvt.rn.bf16x2.f32 %0, %1, %2;\n" : "=r"(r) : "f"(hi), "f"(lo));
  return r;
}

__global__ __launch_bounds__(512, 1)
void qattn_kernel(const float* __restrict__ V, float* __restrict__ Out) {
  extern __shared__ char smem[];
  const uint32_t sbase = (uint32_t)__cvta_generic_to_shared(smem);
  const int b = blockIdx.y, it = blockIdx.x, tid = threadIdx.x;
  const int lane = tid & 31, warp = tid >> 5;
  const int warpM = warp >> 2, warpN = warp & 3;

  // stage A tile [128 x 512] as 8 swizzled [128x64] kc-tiles
  const unsigned short* gA = g_AQ + (size_t)(b * Sn + it * 128) * KKn;
#pragma unroll
  for (int m = 0; m < 16; ++m) {
    int chunk = tid + m * 512;          // 8192 16B chunks
    int kc = chunk >> 10, cr = chunk & 1023;
    int r = cr >> 3, cc = cr & 7;
    cp16(sbase + SM_A + kc * 16384 + swz(r, cc),
         gA + (size_t)r * KKn + kc * 64 + cc * 8);
  }
  asm volatile("cp.async.commit_group;\n" ::: "memory");

  // V -> bf16 smem, fp32 colsum partials
  const float* gV = V + (size_t)b * Sn * 8;
  {
    int e = tid & 7, jg = tid >> 3;
    float part = 0.f;
#pragma unroll
    for (int k = 0; k < 16; ++k) {
      int j = jg + k * 64;
      float v = gV[j * 8 + e];
      part += v;
      *reinterpret_cast<unsigned short*>(smem + SM_V + (j * 8 + e) * 2) = f2bf(v);
    }
    *reinterpret_cast<float*>(smem + SM_CS + (jg * 8 + e) * 4) = part;
  }
  __syncthreads();
  if (tid < 8) {
    float s = 0.f;
    for (int g2 = 0; g2 < 64; ++g2)
      s += *reinterpret_cast<float*>(smem + SM_CS + (g2 * 8 + tid) * 4);
    *reinterpret_cast<float*>(smem + SM_SV + tid * 4) = s;
  }

  const unsigned short* gBRb = g_BR + (size_t)b * Sn * KKn;
  const unsigned short* gBIb = g_BI + (size_t)b * Sn * KKn;
  auto prefetchB = [&](int step, int bufsel) {
    int jt = step >> 3, kc = step & 7;
    const unsigned short* sR = gBRb + (size_t)jt * 128 * KKn + kc * 64;
    const unsigned short* sI = gBIb + (size_t)jt * 128 * KKn + kc * 64;
    uint32_t dR = sbase + (bufsel ? SM_B1R : SM_B0R);
    uint32_t dI = sbase + (bufsel ? SM_B1I : SM_B0I);
#pragma unroll
    for (int m = 0; m < 2; ++m) {
      int chunk = tid + m * 512;
      int r = chunk >> 3, cc = chunk & 7;
      uint32_t so = swz(r, cc);
      cp16(dR + so, sR + (size_t)r * KKn + cc * 8);
      cp16(dI + so, sI + (size_t)r * KKn + cc * 8);
    }
    asm volatile("cp.async.commit_group;\n" ::: "memory");
  };
  prefetchB(0, 0);

  float accR[2][4][4], accI[2][4][4], accO[2][4];
#pragma unroll
  for (int m = 0; m < 2; ++m)
#pragma unroll
    for (int n = 0; n < 4; ++n) {
#pragma unroll
      for (int x = 0; x < 4; ++x) { accR[m][n][x] = 0.f; accI[m][n][x] = 0.f; accO[m][x] = 0.f; }
    }

  const int lr = lane & 15, lchunk = lane >> 4;        // A ldmatrix addressing
  const int brow = (lane & 7) + ((lane >> 4) << 3);    // B ldmatrix addressing
  const int bco  = (lane >> 3) & 1;

  for (int step = 0; step < 64; ++step) {              // (jt,kc) linearized
    const int buf = step & 1;
    if (step + 1 < 64) {
      prefetchB(step + 1, buf ^ 1);
      asm volatile("cp.async.wait_group 1;\n" ::: "memory");
    } else {
      asm volatile("cp.async.wait_group 0;\n" ::: "memory");
    }
    __syncthreads();

    const int kc = step & 7;
    const uint32_t atile  = sbase + SM_A + kc * 16384;
    const uint32_t brTile = sbase + (buf ? SM_B1R : SM_B0R);
    const uint32_t biTile = sbase + (buf ? SM_B1I : SM_B0I);

#pragma unroll
    for (int k16 = 0; k16 < 4; ++k16) {
      uint32_t aF[2][4], bRF[2][4], bIF[2][4];
      ldsm_x4(aF[0], atile + swz(warpM * 32 + lr,      k16 * 2 + lchunk));
      ldsm_x4(aF[1], atile + swz(warpM * 32 + 16 + lr, k16 * 2 + lchunk));
      ldsm_x4(bRF[0], brTile + swz(warpN * 32 + brow,      k16 * 2 + bco));
      ldsm_x4(bRF[1], brTile + swz(warpN * 32 + 16 + brow, k16 * 2 + bco));
      ldsm_x4(bIF[0], biTile + swz(warpN * 32 + brow,      k16 * 2 + bco));
      ldsm_x4(bIF[1], biTile + swz(warpN * 32 + 16 + brow, k16 * 2 + bco));
#pragma unroll
      for (int m = 0; m < 2; ++m)
#pragma unroll
        for (int nf = 0; nf < 4; ++nf) {
          mma16816(accR[m][nf], aF[m], bRF[nf >> 1][(nf & 1) * 2], bRF[nf >> 1][(nf & 1) * 2 + 1]);
          mma16816(accI[m][nf], aF[m], bIF[nf >> 1][(nf & 1) * 2], bIF[nf >> 1][(nf & 1) * 2 + 1]);
        }
    }

    if (kc == 7) {  // j-tile done: P = 2*fid (bf16 A-frags) -> P@V
      const int jt = step >> 3;
      uint32_t vf[2][2];
#pragma unroll
      for (int q = 0; q < 2; ++q)
        ldsm_x2t(vf[q], sbase + SM_V +
                 (uint32_t)((jt * 128 + warpN * 32 + q * 16 + (lane & 15)) * 16));
      const float sc = 2.0f / 65536.0f;
#pragma unroll
      for (int m = 0; m < 2; ++m)
#pragma unroll
        for (int q = 0; q < 2; ++q) {
          const int n0 = 2 * q, n1 = 2 * q + 1;
          float p[8];
#pragma unroll
          for (int x = 0; x < 4; ++x) {
            p[x]     = (accR[m][n0][x] * accR[m][n0][x] + accI[m][n0][x] * accI[m][n0][x]) * sc;
            p[4 + x] = (accR[m][n1][x] * accR[m][n1][x] + accI[m][n1][x] * accI[m][n1][x]) * sc;
          }
          uint32_t pa[4] = { pack2(p[0], p[1]), pack2(p[2], p[3]),
                             pack2(p[4], p[5]), pack2(p[6], p[7]) };
          mma16816(accO[m], pa, vf[q][0], vf[q][1]);
        }
#pragma unroll
      for (int m = 0; m < 2; ++m)
#pragma unroll
        for (int n = 0; n < 4; ++n)
#pragma unroll
          for (int x = 0; x < 4; ++x) { accR[m][n][x] = 0.f; accI[m][n][x] = 0.f; }
    }
    __syncthreads();
  }

  // reduce 4 warpN partials, subtract colsum(V), store
  {
    float* red = reinterpret_cast<float*>(smem + SM_RED) + warpN * (128 * 8);
    const int g = lane >> 2, tg = lane & 3;
#pragma unroll
    for (int m = 0; m < 2; ++m) {
      int r0 = warpM * 32 + m * 16 + g;
      red[r0 * 8 + 2 * tg]           = accO[m][0];
      red[r0 * 8 + 2 * tg + 1]       = accO[m][1];
      red[(r0 + 8) * 8 + 2 * tg]     = accO[m][2];
      red[(r0 + 8) * 8 + 2 * tg + 1] = accO[m][3];
    }
  }
  __syncthreads();
  const float* redall = reinterpret_cast<const float*>(smem + SM_RED);
#pragma unroll
  for (int rep = 0; rep < 2; ++rep) {
    int idx = tid + rep * 512;       // over [128][8]
    int e = idx & 7;
    float v = redall[idx] + redall[1024 + idx] + redall[2048 + idx] + redall[3072 + idx]
            - *reinterpret_cast<const float*>(smem + SM_SV + e * 4);
    Out[(size_t)(b * Sn + it * 128) * 8 + idx] = v;
  }
}

// ---------- launch ----------
extern "C" void kernel_launch(void* const* d_in, const int* in_sizes, int n_in,
                              void* d_out, int out_size) {
  (void)in_sizes; (void)n_in; (void)out_size;
  const float* Q = (const float*)d_in[0];
  const float* K = (const float*)d_in[1];
  const float* V = (const float*)d_in[2];
  float* Out = (float*)d_out;

  dim3 g1(Bn * Sn, 2);
  iqp_amp_kernel<<<g1, 256>>>(Q, K);

  cudaFuncSetAttribute(qattn_kernel, cudaFuncAttributeMaxDynamicSharedMemorySize, SM_TOTAL);
  dim3 g2(8, Bn);
  qattn_kernel<<<g2, 512, SM_TOTAL>>>(V, Out);
}

// round 3
// speedup vs baseline: 1.0180x; 1.0180x over previous
#include <cuda_runtime.h>
#include <cuda_bf16.h>
#include <cstdint>

#define DEV_INLINE __device__ __forceinline__

constexpr int Bn  = 16;
constexpr int Sn  = 1024;
constexpr int KKn = 512;   // GEMM K = 2 * 256 basis states

// bf16 scratch planes (raw ushort bits).
// AQ row i: [cos(phi_q)(256) | sin(phi_q)(256)]
// BR row j: [cos(phi_k)      | sin(phi_k)     ]  -> re = AQ.BR
// BI row j: [sin(phi_k)      | -cos(phi_k)    ]  -> im = AQ.BI
__device__ __align__(128) unsigned short g_AQ[Bn * Sn * KKn];
__device__ __align__(128) unsigned short g_BR[Bn * Sn * KKn];
__device__ __align__(128) unsigned short g_BI[Bn * Sn * KKn];

DEV_INLINE unsigned short f2bf(float x) {
  __nv_bfloat16 h = __float2bfloat16(x);
  return *reinterpret_cast<unsigned short*>(&h);
}

// ---------- kernel 1: IQP amplitudes ----------
__global__ void iqp_amp_kernel(const float* __restrict__ Q, const float* __restrict__ K) {
  const int tok = blockIdx.x, isK = blockIdx.y;
  const float* X = isK ? K : Q;
  __shared__ float xs[8];
  const int z = threadIdx.x;
  if (z < 8) xs[z] = X[tok * 8 + z];
  __syncthreads();
  float sq = 0.f, L = 0.f;
#pragma unroll
  for (int i = 0; i < 8; ++i) {
    float xi = xs[i];
    sq += xi * xi;
    L  += ((z >> i) & 1) ? -xi : xi;
  }
  const float phase = -0.5f * L - 0.25f * (L * L - sq);
  float s, c;
  sincosf(phase, &s, &c);
  const size_t base = (size_t)tok * KKn;
  if (!isK) {
    g_AQ[base + z]       = f2bf(c);
    g_AQ[base + 256 + z] = f2bf(s);
  } else {
    g_BR[base + z]       = f2bf(c);
    g_BR[base + 256 + z] = f2bf(s);
    g_BI[base + z]       = f2bf(s);
    g_BI[base + 256 + z] = f2bf(-c);
  }
}

// ---------- kernel 2: fused fid-attention ----------
// smem byte offsets
constexpr int SM_A   = 0;        // 8 kc-tiles * [128x64] bf16 = 131072
constexpr int SM_B0R = 131072;   // 16384 each
constexpr int SM_B0I = 147456;
constexpr int SM_B1R = 163840;
constexpr int SM_B1I = 180224;
constexpr int SM_V   = 196608;   // [1024][8] bf16 = 16384
constexpr int SM_CS  = 212992;   // colsum partials [64][8] f32
constexpr int SM_SV  = 215040;   // colsum(V)[8] f32
constexpr int SM_RED = 131072;   // O-reduce, reuses B0R after loop
constexpr int SM_TOTAL = 215072;

DEV_INLINE uint32_t swz(int r, int cchunk) {   // 128B rows, 16B-chunk XOR swizzle
  return (uint32_t)(r * 128 + ((cchunk ^ (r & 7)) << 4));
}
DEV_INLINE void cp16(uint32_t dst, const void* src) {
  asm volatile("cp.async.cg.shared.global [%0], [%1], 16;\n" :: "r"(dst), "l"(src) : "memory");
}
DEV_INLINE void ldsm_x4(uint32_t* r, uint32_t a) {
  asm volatile("ldmatrix.sync.aligned.m8n8.x4.shared.b16 {%0,%1,%2,%3}, [%4];\n"
               : "=r"(r[0]), "=r"(r[1]), "=r"(r[2]), "=r"(r[3]) : "r"(a));
}
DEV_INLINE void ldsm_x2t(uint32_t* r, uint32_t a) {
  asm volatile("ldmatrix.sync.aligned.m8n8.x2.trans.shared.b16 {%0,%1}, [%2];\n"
               : "=r"(r[0]), "=r"(r[1]) : "r"(a));
}
DEV_INLINE void mma16816(float* c, const uint32_t* a, uint32_t b0, uint32_t b1) {
  asm volatile(
      "mma.sync.aligned.m16n8k16.row.col.f32.bf16.bf16.f32 "
      "{%0,%1,%2,%3}, {%4,%5,%6,%7}, {%8,%9}, {%0,%1,%2,%3};\n"
      : "+f"(c[0]), "+f"(c[1]), "+f"(c[2]), "+f"(c[3])
      : "r"(a[0]), "r"(a[1]), "r"(a[2]), "r"(a[3]), "r"(b0), "r"(b1));
}
DEV_INLINE uint32_t pack2(float lo, float hi) {   // -> {hi:lo} bf16x2
  uint32_t r;
  asm("cvt.rn.bf16x2.f32 %0, %1, %2;\n" : "=r"(r) : "f"(hi), "f"(lo));
  return r;
}

__global__ __launch_bounds__(512, 1)
void qattn_kernel(const float* __restrict__ V, float* __restrict__ Out) {
  extern __shared__ char smem[];
  const uint32_t sbase = (uint32_t)__cvta_generic_to_shared(smem);
  const int b = blockIdx.y, it = blockIdx.x, tid = threadIdx.x;
  const int lane = tid & 31, warp = tid >> 5;
  const int warpM = warp >> 2, warpN = warp & 3;

  // stage A tile [128 x 512] as 8 swizzled [128x64] kc-tiles
  const unsigned short* gA = g_AQ + (size_t)(b * Sn + it * 128) * KKn;
#pragma unroll
  for (int m = 0; m < 16; ++m) {
    int chunk = tid + m * 512;          // 8192 16B chunks
    int kc = chunk >> 10, cr = chunk & 1023;
    int r = cr >> 3, cc = cr & 7;
    cp16(sbase + SM_A + kc * 16384 + swz(r, cc),
         gA + (size_t)r * KKn + kc * 64 + cc * 8);
  }
  asm volatile("cp.async.commit_group;\n" ::: "memory");

  // V -> bf16 smem, fp32 colsum partials
  const float* gV = V + (size_t)b * Sn * 8;
  {
    int e = tid & 7, jg = tid >> 3;
    float part = 0.f;
#pragma unroll
    for (int k = 0; k < 16; ++k) {
      int j = jg + k * 64;
      float v = gV[j * 8 + e];
      part += v;
      *reinterpret_cast<unsigned short*>(smem + SM_V + (j * 8 + e) * 2) = f2bf(v);
    }
    *reinterpret_cast<float*>(smem + SM_CS + (jg * 8 + e) * 4) = part;
  }
  __syncthreads();
  if (tid < 8) {
    float s = 0.f;
    for (int g2 = 0; g2 < 64; ++g2)
      s += *reinterpret_cast<float*>(smem + SM_CS + (g2 * 8 + tid) * 4);
    *reinterpret_cast<float*>(smem + SM_SV + tid * 4) = s;
  }

  const unsigned short* gBRb = g_BR + (size_t)b * Sn * KKn;
  const unsigned short* gBIb = g_BI + (size_t)b * Sn * KKn;
  auto prefetchB = [&](int step, int bufsel) {
    int jt = step >> 3, kc = step & 7;
    const unsigned short* sR = gBRb + (size_t)jt * 128 * KKn + kc * 64;
    const unsigned short* sI = gBIb + (size_t)jt * 128 * KKn + kc * 64;
    uint32_t dR = sbase + (bufsel ? SM_B1R : SM_B0R);
    uint32_t dI = sbase + (bufsel ? SM_B1I : SM_B0I);
#pragma unroll
    for (int m = 0; m < 2; ++m) {
      int chunk = tid + m * 512;
      int r = chunk >> 3, cc = chunk & 7;
      uint32_t so = swz(r, cc);
      cp16(dR + so, sR + (size_t)r * KKn + cc * 8);
      cp16(dI + so, sI + (size_t)r * KKn + cc * 8);
    }
    asm volatile("cp.async.commit_group;\n" ::: "memory");
  };
  prefetchB(0, 0);

  float accR[2][4][4], accI[2][4][4], accO[2][4];
#pragma unroll
  for (int m = 0; m < 2; ++m)
#pragma unroll
    for (int n = 0; n < 4; ++n) {
#pragma unroll
      for (int x = 0; x < 4; ++x) { accR[m][n][x] = 0.f; accI[m][n][x] = 0.f; accO[m][x] = 0.f; }
    }

  const int lr = lane & 15, lchunk = lane >> 4;        // A ldmatrix addressing
  const int brow = (lane & 7) + ((lane >> 4) << 3);    // B ldmatrix addressing
  const int bco  = (lane >> 3) & 1;

  for (int step = 0; step < 64; ++step) {              // (jt,kc) linearized
    const int buf = step & 1;
    if (step + 1 < 64) {
      prefetchB(step + 1, buf ^ 1);
      asm volatile("cp.async.wait_group 1;\n" ::: "memory");
    } else {
      asm volatile("cp.async.wait_group 0;\n" ::: "memory");
    }
    __syncthreads();

    const int kc = step & 7;
    const uint32_t atile  = sbase + SM_A + kc * 16384;
    const uint32_t brTile = sbase + (buf ? SM_B1R : SM_B0R);
    const uint32_t biTile = sbase + (buf ? SM_B1I : SM_B0I);

#pragma unroll
    for (int k16 = 0; k16 < 4; ++k16) {
      uint32_t aF[2][4], bRF[2][4], bIF[2][4];
      ldsm_x4(aF[0], atile + swz(warpM * 32 + lr,      k16 * 2 + lchunk));
      ldsm_x4(aF[1], atile + swz(warpM * 32 + 16 + lr, k16 * 2 + lchunk));
      ldsm_x4(bRF[0], brTile + swz(warpN * 32 + brow,      k16 * 2 + bco));
      ldsm_x4(bRF[1], brTile + swz(warpN * 32 + 16 + brow, k16 * 2 + bco));
      ldsm_x4(bIF[0], biTile + swz(warpN * 32 + brow,      k16 * 2 + bco));
      ldsm_x4(bIF[1], biTile + swz(warpN * 32 + 16 + brow, k16 * 2 + bco));
#pragma unroll
      for (int m = 0; m < 2; ++m)
#pragma unroll
        for (int nf = 0; nf < 4; ++nf) {
          mma16816(accR[m][nf], aF[m], bRF[nf >> 1][(nf & 1) * 2], bRF[nf >> 1][(nf & 1) * 2 + 1]);
          mma16816(accI[m][nf], aF[m], bIF[nf >> 1][(nf & 1) * 2], bIF[nf >> 1][(nf & 1) * 2 + 1]);
        }
    }

    if (kc == 7) {  // j-tile done: P = 2*fid (bf16 A-frags) -> P@V
      const int jt = step >> 3;
      uint32_t vf[2][2];
#pragma unroll
      for (int q = 0; q < 2; ++q)
        ldsm_x2t(vf[q], sbase + SM_V +
                 (uint32_t)((jt * 128 + warpN * 32 + q * 16 + (lane & 15)) * 16));
      const float sc = 2.0f / 65536.0f;
#pragma unroll
      for (int m = 0; m < 2; ++m)
#pragma unroll
        for (int q = 0; q < 2; ++q) {
          const int n0 = 2 * q, n1 = 2 * q + 1;
          float p[8];
#pragma unroll
          for (int x = 0; x < 4; ++x) {
            p[x]     = (accR[m][n0][x] * accR[m][n0][x] + accI[m][n0][x] * accI[m][n0][x]) * sc;
            p[4 + x] = (accR[m][n1][x] * accR[m][n1][x] + accI[m][n1][x] * accI[m][n1][x]) * sc;
          }
          uint32_t pa[4] = { pack2(p[0], p[1]), pack2(p[2], p[3]),
                             pack2(p[4], p[5]), pack2(p[6], p[7]) };
          mma16816(accO[m], pa, vf[q][0], vf[q][1]);
        }
#pragma unroll
      for (int m = 0; m < 2; ++m)
#pragma unroll
        for (int n = 0; n < 4; ++n)
#pragma unroll
          for (int x = 0; x < 4; ++x) { accR[m][n][x] = 0.f; accI[m][n][x] = 0.f; }
    }
    __syncthreads();
  }

  // reduce 4 warpN partials, subtract colsum(V), store
  {
    float* red = reinterpret_cast<float*>(smem + SM_RED) + warpN * (128 * 8);
    const int g = lane >> 2, tg = lane & 3;
#pragma unroll
    for (int m = 0; m < 2; ++m) {
      int r0 = warpM * 32 + m * 16 + g;
      red[r0 * 8 + 2 * tg]           = accO[m][0];
      red[r0 * 8 + 2 * tg + 1]       = accO[m][1];
      red[(r0 + 8) * 8 + 2 * tg]     = accO[m][2];
      red[(r0 + 8) * 8 + 2 * tg + 1] = accO[m][3];
    }
  }
  __syncthreads();
  const float* redall = reinterpret_cast<const float*>(smem + SM_RED);
#pragma unroll
  for (int rep = 0; rep < 2; ++rep) {
    int idx = tid + rep * 512;       // over [128][8]
    int e = idx & 7;
    float v = redall[idx] + redall[1024 + idx] + redall[2048 + idx] + redall[3072 + idx]
            - *reinterpret_cast<const float*>(smem + SM_SV + e * 4);
    Out[(size_t)(b * Sn + it * 128) * 8 + idx] = v;
  }
}

// ---------- launch ----------
extern "C" void kernel_launch(void* const* d_in, const int* in_sizes, int n_in,
                              void* d_out, int out_size) {
  (void)in_sizes; (void)n_in; (void)out_size;
  const float* Q = (const float*)d_in[0];
  const float* K = (const float*)d_in[1];
  const float* V = (const float*)d_in[2];
  float* Out = (float*)d_out;

  dim3 g1(Bn * Sn, 2);
  iqp_amp_kernel<<<g1, 256>>>(Q, K);

  cudaFuncSetAttribute(qattn_kernel, cudaFuncAttributeMaxDynamicSharedMemorySize, SM_TOTAL);
  dim3 g2(8, Bn);
  qattn_kernel<<<g2, 512, SM_TOTAL>>>(V, Out);
}

// round 5
// speedup vs baseline: 1.0418x; 1.0234x over previous
#include <cuda_runtime.h>
#include <cuda_bf16.h>
#include <cstdint>
#define DI __device__ __forceinline__

constexpr int Bn=16, Sn=1024, KKn=512;
__device__ __align__(128) unsigned short g_AQ[Bn*Sn*KKn];
__device__ __align__(128) unsigned short g_BR[Bn*Sn*KKn];
__device__ __align__(128) unsigned short g_BI[Bn*Sn*KKn];

DI unsigned short f2bf(float x){ __nv_bfloat16 h=__float2bfloat16(x); return *(unsigned short*)&h; }

// ---------- kernel 1: IQP amplitudes (16 tokens/block, fast sincos) ----------
__global__ void iqp_amp_kernel(const float* __restrict__ Q, const float* __restrict__ K){
  const int isK=blockIdx.y;
  const float* X = isK?K:Q;
  const int t0 = blockIdx.x*16;
  __shared__ float xs[16][8];
  const int tid=threadIdx.x;
  if(tid<128) xs[tid>>3][tid&7]=X[t0*8+tid];
  __syncthreads();
  const int z=tid;
#pragma unroll 4
  for(int t=0;t<16;++t){
    float sq=0.f,L=0.f;
#pragma unroll
    for(int i=0;i<8;++i){ float xi=xs[t][i]; sq+=xi*xi; L+=((z>>i)&1)?-xi:xi; }
    float ph=-0.5f*L-0.25f*(L*L-sq), s,c; __sincosf(ph,&s,&c);
    size_t base=(size_t)(t0+t)*KKn;
    if(!isK){ g_AQ[base+z]=f2bf(c); g_AQ[base+256+z]=f2bf(s); }
    else { g_BR[base+z]=f2bf(c); g_BR[base+256+z]=f2bf(s);
           g_BI[base+z]=f2bf(s); g_BI[base+256+z]=f2bf(-c); }
  }
}

// ---------- kernel 2: fused fid-attention (mma.sync, 64x32 warp tiles) ----------
constexpr int SM_A=0;            // 8 x [128x64] bf16 = 131072
constexpr int SM_B=131072;       // 2 sets x (R,I) x 16384 = 65536
constexpr int SM_V=196608;       // [1024][8] bf16 = 16384
constexpr int SM_RED=212992;     // 4 x [128][8] f32 = 16384
constexpr int SM_CS=229376;      // [32][8] f32
constexpr int SM_SV=230400;      // [8] f32
constexpr int SM_TOTAL=230432;

DI uint32_t swz(int r,int c){ return (uint32_t)(r*128 + ((c^(r&7))<<4)); }
DI void cp16(uint32_t d,const void* s){ asm volatile("cp.async.cg.shared.global [%0],[%1],16;\n"::"r"(d),"l"(s):"memory"); }
DI void cpc(){ asm volatile("cp.async.commit_group;\n":::"memory"); }
DI void ldsm_x4(uint32_t* r,uint32_t a){
  asm volatile("ldmatrix.sync.aligned.m8n8.x4.shared.b16 {%0,%1,%2,%3},[%4];\n"
    :"=r"(r[0]),"=r"(r[1]),"=r"(r[2]),"=r"(r[3]):"r"(a));
}
DI void ldsm_x2t(uint32_t* r,uint32_t a){
  asm volatile("ldmatrix.sync.aligned.m8n8.x2.trans.shared.b16 {%0,%1},[%2];\n"
    :"=r"(r[0]),"=r"(r[1]):"r"(a));
}
DI void mma16816(float* c,const uint32_t* a,uint32_t b0,uint32_t b1){
  asm volatile("mma.sync.aligned.m16n8k16.row.col.f32.bf16.bf16.f32 {%0,%1,%2,%3},{%4,%5,%6,%7},{%8,%9},{%0,%1,%2,%3};\n"
    :"+f"(c[0]),"+f"(c[1]),"+f"(c[2]),"+f"(c[3])
    :"r"(a[0]),"r"(a[1]),"r"(a[2]),"r"(a[3]),"r"(b0),"r"(b1));
}
DI uint32_t pack2(float lo,float hi){ uint32_t r; asm("cvt.rn.bf16x2.f32 %0,%1,%2;\n":"=r"(r):"f"(hi),"f"(lo)); return r; }

__global__ __launch_bounds__(256,1)
void qattn_kernel(const float* __restrict__ V, float* __restrict__ Out){
  extern __shared__ char smem[];
  const uint32_t sb=(uint32_t)__cvta_generic_to_shared(smem);
  const int b=blockIdx.y, it=blockIdx.x, tid=threadIdx.x;
  const int lane=tid&31, warp=tid>>5;
  const int wm=warp>>2, wn=warp&3;   // 2 x 4 warp grid, tiles 64(M) x 32(N)

  // stage A [128x512] as 8 swizzled [128x64] kc-tiles
  const unsigned short* gA = g_AQ + (size_t)(b*Sn+it*128)*KKn;
#pragma unroll
  for(int m=0;m<32;++m){
    int ch=tid+m*256, kc=ch>>10, cr=ch&1023, r=cr>>3, cx=cr&7;
    cp16(sb+SM_A+kc*16384+swz(r,cx), gA+(size_t)r*KKn+kc*64+cx*8);
  }
  const unsigned short* gR = g_BR + (size_t)b*Sn*KKn;
  const unsigned short* gI = g_BI + (size_t)b*Sn*KKn;
  auto loadB=[&](int c,int set){
    int jt=c>>3, kc=c&7;
    const unsigned short* sR=gR+(size_t)jt*128*KKn+kc*64;
    const unsigned short* sI=gI+(size_t)jt*128*KKn+kc*64;
    uint32_t dR=sb+SM_B+set*32768, dIa=dR+16384;
#pragma unroll
    for(int m=0;m<4;++m){
      int ch=tid+m*256, r=ch>>3, cx=ch&7;
      uint32_t so=swz(r,cx);
      cp16(dR+so,  sR+(size_t)r*KKn+cx*8);
      cp16(dIa+so, sI+(size_t)r*KKn+cx*8);
    }
  };
  loadB(0,0); cpc();   // G0 = A + B0
  loadB(1,1); cpc();   // G1 = B1

  // V -> bf16 smem + colsum
  const float* gV = V + (size_t)b*Sn*8;
  {
    int e=tid&7, jg=tid>>3; float part=0.f;
#pragma unroll
    for(int k=0;k<32;++k){
      int j=jg+k*32; float v=gV[j*8+e]; part+=v;
      *(unsigned short*)(smem+SM_V+(j*8+e)*2)=f2bf(v);
    }
    *(float*)(smem+SM_CS+(jg*8+e)*4)=part;
  }
  __syncthreads();
  if(tid<8){ float s=0.f; for(int g=0;g<32;++g) s+=*(float*)(smem+SM_CS+(g*8+tid)*4);
             *(float*)(smem+SM_SV+tid*4)=s; }

  float accR[4][4][4], accI[4][4][4], accO[4][4];
#pragma unroll
  for(int m=0;m<4;++m)
#pragma unroll
    for(int n=0;n<4;++n)
#pragma unroll
      for(int x=0;x<4;++x){ accR[m][n][x]=0.f; accI[m][n][x]=0.f; accO[m][x]=0.f; }

  const int lr=lane&15, lch=lane>>4;
  const int brow=(lane&7)+((lane>>4)<<3), bco=(lane>>3)&1;
  const float sc=2.0f/65536.0f;

  for(int c=0;c<64;++c){
    const int kc=c&7, bs=c&1, jt=c>>3;
    if(c+2<64) asm volatile("cp.async.wait_group 1;\n":::"memory");
    else       asm volatile("cp.async.wait_group 0;\n":::"memory");
    __syncthreads();
    const uint32_t at=sb+SM_A+kc*16384, bt=sb+SM_B+bs*32768;

#pragma unroll
    for(int k16=0;k16<4;++k16){
      uint32_t aF[4][4], bR[2][4], bI[2][4];
#pragma unroll
      for(int m=0;m<4;++m) ldsm_x4(aF[m], at+swz(wm*64+m*16+lr, k16*2+lch));
#pragma unroll
      for(int h=0;h<2;++h){
        ldsm_x4(bR[h], bt+swz(wn*32+h*16+brow, k16*2+bco));
        ldsm_x4(bI[h], bt+16384+swz(wn*32+h*16+brow, k16*2+bco));
      }
#pragma unroll
      for(int m=0;m<4;++m)
#pragma unroll
        for(int nf=0;nf<4;++nf){
          mma16816(accR[m][nf], aF[m], bR[nf>>1][(nf&1)*2], bR[nf>>1][(nf&1)*2+1]);
          mma16816(accI[m][nf], aF[m], bI[nf>>1][(nf&1)*2], bI[nf>>1][(nf&1)*2+1]);
        }
    }

    if(kc==7){  // j-tile done: P = 2*fid (bf16 A-frags in-register) -> P@V
      uint32_t vf[2][2];
#pragma unroll
      for(int q=0;q<2;++q)
        ldsm_x2t(vf[q], sb+SM_V+(uint32_t)((jt*128+wn*32+q*16+(lane&15))*16));
#pragma unroll
      for(int m=0;m<4;++m)
#pragma unroll
        for(int q=0;q<2;++q){
          const int n0=2*q, n1=2*q+1;
          float p[8];
#pragma unroll
          for(int x=0;x<4;++x){
            p[x]  =(accR[m][n0][x]*accR[m][n0][x]+accI[m][n0][x]*accI[m][n0][x])*sc;
            p[4+x]=(accR[m][n1][x]*accR[m][n1][x]+accI[m][n1][x]*accI[m][n1][x])*sc;
          }
          uint32_t pa[4]={pack2(p[0],p[1]),pack2(p[2],p[3]),pack2(p[4],p[5]),pack2(p[6],p[7])};
          mma16816(accO[m], pa, vf[q][0], vf[q][1]);
        }
#pragma unroll
      for(int m=0;m<4;++m)
#pragma unroll
        for(int n=0;n<4;++n)
#pragma unroll
          for(int x=0;x<4;++x){ accR[m][n][x]=0.f; accI[m][n][x]=0.f; }
    }
    __syncthreads();
    if(c+2<64){ loadB(c+2,bs); cpc(); }
  }

  // reduce 4 warpN partials, subtract colsum(V), store
  {
    float* red=(float*)(smem+SM_RED)+wn*1024;
    const int g=lane>>2, e0=(lane&3)*2;
#pragma unroll
    for(int m=0;m<4;++m){
      int r0=wm*64+m*16+g;
      red[r0*8+e0]=accO[m][0];     red[r0*8+e0+1]=accO[m][1];
      red[(r0+8)*8+e0]=accO[m][2]; red[(r0+8)*8+e0+1]=accO[m][3];
    }
  }
  __syncthreads();
  const float* redall=(const float*)(smem+SM_RED);
  size_t ob=(size_t)(b*Sn+it*128)*8;
#pragma unroll
  for(int rep=0;rep<4;++rep){
    int idx=tid+rep*256, e=idx&7;
    float v=redall[idx]+redall[1024+idx]+redall[2048+idx]+redall[3072+idx]
           -*(const float*)(smem+SM_SV+e*4);
    Out[ob+idx]=v;
  }
}

extern "C" void kernel_launch(void* const* d_in,const int* in_sizes,int n_in,void* d_out,int out_size){
  (void)in_sizes;(void)n_in;(void)out_size;
  const float* Q=(const float*)d_in[0];
  const float* K=(const float*)d_in[1];
  const float* V=(const float*)d_in[2];
  float* Out=(float*)d_out;
  dim3 g1(Bn*Sn/16,2);
  iqp_amp_kernel<<<g1,256>>>(Q,K);
  cudaFuncSetAttribute(qattn_kernel,cudaFuncAttributeMaxDynamicSharedMemorySize,SM_TOTAL);
  dim3 g2(8,Bn);
  qattn_kernel<<<g2,256,SM_TOTAL>>>(V,Out);
}

// round 6
// speedup vs baseline: 1.1387x; 1.0930x over previous
#include <cuda_runtime.h>
#include <cuda_bf16.h>
#include <cstdint>
#define DI __device__ __forceinline__

constexpr int Bn=16, Sn=1024, W=768;
__device__ __align__(128) unsigned short g_A[Bn*Sn*W];
__device__ __align__(128) unsigned short g_B[Bn*Sn*W];

DI unsigned short f2bf(float x){ __nv_bfloat16 h=__float2bfloat16(x); return *(unsigned short*)&h; }

// kernel 1: IQP amplitudes. Row: [c(256)|s(256)|d(256)], d = c-s (A) or c+s (B)
__global__ void iqp_amp_kernel(const float* __restrict__ Q, const float* __restrict__ K){
  const int isK=blockIdx.y;
  const float* X = isK?K:Q;
  const int t0 = blockIdx.x*16;
  __shared__ float xs[16][8];
  const int tid=threadIdx.x;
  if(tid<128) xs[tid>>3][tid&7]=X[t0*8+tid];
  __syncthreads();
  const int z=tid;
  unsigned short* G = isK? g_B : g_A;
#pragma unroll 4
  for(int t=0;t<16;++t){
    float sq=0.f,L=0.f;
#pragma unroll
    for(int i=0;i<8;++i){ float xi=xs[t][i]; sq+=xi*xi; L+=((z>>i)&1)?-xi:xi; }
    float ph=-0.5f*L-0.25f*(L*L-sq), s,c; __sincosf(ph,&s,&c);
    size_t base=(size_t)(t0+t)*W;
    G[base+z]=f2bf(c); G[base+256+z]=f2bf(s);
    G[base+512+z]=f2bf(isK? c+s : c-s);
  }
}

// kernel 2: fused fid-attention
constexpr int SM_A=0;        // 8 x [128x64] resident (c,s planes)
constexpr int SM_AD=131072;  // 2 x 16384 streamed A d-plane
constexpr int SM_B=163840;   // 2 x 16384 streamed B chunks
constexpr int SM_V=196608;   // [1024][8] bf16
constexpr int SM_CS=212992;  // [64][8] f32
constexpr int SM_SV=215040;  // [8] f32
constexpr int SM_RED=0;      // reuse A after loop
constexpr int SM_TOTAL=215072;

DI uint32_t swz(int r,int c){ return (uint32_t)(r*128 + ((c^(r&7))<<4)); }
DI void cp16(uint32_t d,const void* s){ asm volatile("cp.async.cg.shared.global [%0],[%1],16;\n"::"r"(d),"l"(s):"memory"); }
DI void cpc(){ asm volatile("cp.async.commit_group;\n":::"memory"); }
DI void ldsm_x4(uint32_t* r,uint32_t a){
  asm volatile("ldmatrix.sync.aligned.m8n8.x4.shared.b16 {%0,%1,%2,%3},[%4];\n"
    :"=r"(r[0]),"=r"(r[1]),"=r"(r[2]),"=r"(r[3]):"r"(a));
}
DI void ldsm_x2t(uint32_t* r,uint32_t a){
  asm volatile("ldmatrix.sync.aligned.m8n8.x2.trans.shared.b16 {%0,%1},[%2];\n"
    :"=r"(r[0]),"=r"(r[1]):"r"(a));
}
DI void mma16816(float* c,const uint32_t* a,uint32_t b0,uint32_t b1){
  asm volatile("mma.sync.aligned.m16n8k16.row.col.f32.bf16.bf16.f32 {%0,%1,%2,%3},{%4,%5,%6,%7},{%8,%9},{%0,%1,%2,%3};\n"
    :"+f"(c[0]),"+f"(c[1]),"+f"(c[2]),"+f"(c[3])
    :"r"(a[0]),"r"(a[1]),"r"(a[2]),"r"(a[3]),"r"(b0),"r"(b1));
}
DI uint32_t pack2(float lo,float hi){ uint32_t r; asm("cvt.rn.bf16x2.f32 %0,%1,%2;\n":"=r"(r):"f"(hi),"f"(lo)); return r; }

__global__ __launch_bounds__(512,1)
void qattn_kernel(const float* __restrict__ V, float* __restrict__ Out){
  extern __shared__ char smem[];
  const uint32_t sb=(uint32_t)__cvta_generic_to_shared(smem);
  const int b=blockIdx.y, it=blockIdx.x, tid=threadIdx.x;
  const int lane=tid&31, warp=tid>>5;
  const int wm=warp>>2, wn=warp&3;   // 4M x 4N warp grid, 32x32 tiles

  const unsigned short* gAi = g_A + (size_t)(b*Sn+it*128)*W;
  const unsigned short* gBb = g_B + (size_t)b*Sn*W;

  // stage resident A (c,s planes: cols 0..511 -> 8 kc-tiles)
#pragma unroll
  for(int m=0;m<16;++m){
    int ch=tid+m*512, kc=ch>>10, cr=ch&1023, r=cr>>3, cx=cr&7;
    cp16(sb+SM_A+kc*16384+swz(r,cx), gAi+(size_t)r*W+kc*64+cx*8);
  }
  auto loadChunk=[&](int step){
    int jt2=step/12, kc2=step-jt2*12, set=step&1;
    const unsigned short* sB=gBb+(size_t)jt2*128*W+kc2*64;
    uint32_t dB=sb+SM_B+set*16384;
#pragma unroll
    for(int m=0;m<2;++m){ int ch=tid+m*512,r=ch>>3,cx=ch&7;
      cp16(dB+swz(r,cx), sB+(size_t)r*W+cx*8); }
    if(kc2>=8){
      const unsigned short* sA=gAi+512+(kc2-8)*64;
      uint32_t dA=sb+SM_AD+set*16384;
#pragma unroll
      for(int m=0;m<2;++m){ int ch=tid+m*512,r=ch>>3,cx=ch&7;
        cp16(dA+swz(r,cx), sA+(size_t)r*W+cx*8); }
    }
    cpc();
  };
  loadChunk(0);   // commits A-resident + chunk0
  loadChunk(1);

  // V -> bf16 smem + colsum
  const float* gV = V + (size_t)b*Sn*8;
  {
    int e=tid&7, jg=tid>>3; float part=0.f;
#pragma unroll
    for(int k=0;k<16;++k){
      int j=jg+k*64; float v=gV[j*8+e]; part+=v;
      *(unsigned short*)(smem+SM_V+(j*8+e)*2)=f2bf(v);
    }
    *(float*)(smem+SM_CS+(jg*8+e)*4)=part;
  }
  __syncthreads();
  if(tid<8){ float s=0.f; for(int g=0;g<64;++g) s+=*(float*)(smem+SM_CS+(g*8+tid)*4);
             *(float*)(smem+SM_SV+tid*4)=s; }

  float accX[2][4][4], accY[2][4][4], accO[2][4];
#pragma unroll
  for(int m=0;m<2;++m)
#pragma unroll
    for(int n=0;n<4;++n)
#pragma unroll
      for(int x=0;x<4;++x){ accX[m][n][x]=0.f; accY[m][n][x]=0.f; accO[m][x]=0.f; }

  const int lr=lane&15, lch=lane>>4;
  const int brow=(lane&7)+((lane>>4)<<3), bco=(lane>>3)&1;
  const float sc=2.0f/65536.0f;

  for(int jt=0;jt<8;++jt){
#pragma unroll
    for(int kc=0;kc<12;++kc){
      const int c=jt*12+kc;
      if(c+1<96) asm volatile("cp.async.wait_group 1;\n":::"memory");
      else       asm volatile("cp.async.wait_group 0;\n":::"memory");
      __syncthreads();
      const uint32_t at=(kc<8)?(sb+SM_A+kc*16384):(sb+SM_AD+(uint32_t)((c&1)*16384));
      const uint32_t bt=sb+SM_B+(uint32_t)((c&1)*16384);
      float (&acc)[2][4][4] = (kc<4)? accX : accY;   // m1->X; m2,m3->Y

#pragma unroll
      for(int k16=0;k16<4;++k16){
        uint32_t aF[2][4], bF[2][4];
        ldsm_x4(aF[0], at+swz(wm*32+lr,    k16*2+lch));
        ldsm_x4(aF[1], at+swz(wm*32+16+lr, k16*2+lch));
        ldsm_x4(bF[0], bt+swz(wn*32+brow,    k16*2+bco));
        ldsm_x4(bF[1], bt+swz(wn*32+16+brow, k16*2+bco));
#pragma unroll
        for(int m=0;m<2;++m)
#pragma unroll
          for(int nf=0;nf<4;++nf)
            mma16816(acc[m][nf], aF[m], bF[nf>>1][(nf&1)*2], bF[nf>>1][(nf&1)*2+1]);
      }

      if(kc==7){  // butterfly: X=m1+m2=re, Y=m2-m1 (m3 accumulates on top -> im)
#pragma unroll
        for(int m=0;m<2;++m)
#pragma unroll
          for(int n=0;n<4;++n)
#pragma unroll
            for(int x=0;x<4;++x){
              float a=accX[m][n][x], b2=accY[m][n][x];
              accX[m][n][x]=a+b2; accY[m][n][x]=b2-a;
            }
      }

      if(kc==11){  // P = 2*fid -> bf16 A-frags -> P@V
        uint32_t vf[2][2];
#pragma unroll
        for(int q=0;q<2;++q)
          ldsm_x2t(vf[q], sb+SM_V+(uint32_t)((jt*128+wn*32+q*16+(lane&15))*16));
#pragma unroll
        for(int m=0;m<2;++m)
#pragma unroll
          for(int q=0;q<2;++q){
            const int n0=2*q, n1=2*q+1;
            float p[8];
#pragma unroll
            for(int x=0;x<4;++x){
              p[x]  =(accX[m][n0][x]*accX[m][n0][x]+accY[m][n0][x]*accY[m][n0][x])*sc;
              p[4+x]=(accX[m][n1][x]*accX[m][n1][x]+accY[m][n1][x]*accY[m][n1][x])*sc;
            }
            uint32_t pa[4]={pack2(p[0],p[1]),pack2(p[2],p[3]),pack2(p[4],p[5]),pack2(p[6],p[7])};
            mma16816(accO[m], pa, vf[q][0], vf[q][1]);
          }
#pragma unroll
        for(int m=0;m<2;++m)
#pragma unroll
          for(int n=0;n<4;++n)
#pragma unroll
            for(int x=0;x<4;++x){ accX[m][n][x]=0.f; accY[m][n][x]=0.f; }
      }
      __syncthreads();
      if(c+2<96) loadChunk(c+2);
    }
  }

  // reduce 4 warpN partials, subtract colsum(V), store
  {
    float* red=(float*)(smem+SM_RED)+wn*1024;
    const int g=lane>>2, e0=(lane&3)*2;
#pragma unroll
    for(int m=0;m<2;++m){
      int r0=wm*32+m*16+g;
      red[r0*8+e0]=accO[m][0];     red[r0*8+e0+1]=accO[m][1];
      red[(r0+8)*8+e0]=accO[m][2]; red[(r0+8)*8+e0+1]=accO[m][3];
    }
  }
  __syncthreads();
  const float* redall=(const float*)(smem+SM_RED);
  size_t ob=(size_t)(b*Sn+it*128)*8;
#pragma unroll
  for(int rep=0;rep<2;++rep){
    int idx=tid+rep*512, e=idx&7;
    float v=redall[idx]+redall[1024+idx]+redall[2048+idx]+redall[3072+idx]
           -*(const float*)(smem+SM_SV+e*4);
    Out[ob+idx]=v;
  }
}

extern "C" void kernel_launch(void* const* d_in,const int* in_sizes,int n_in,void* d_out,int out_size){
  (void)in_sizes;(void)n_in;(void)out_size;
  const float* Q=(const float*)d_in[0];
  const float* K=(const float*)d_in[1];
  const float* V=(const float*)d_in[2];
  float* Out=(float*)d_out;
  dim3 g1(Bn*Sn/16,2);
  iqp_amp_kernel<<<g1,256>>>(Q,K);
  cudaFuncSetAttribute(qattn_kernel,cudaFuncAttributeMaxDynamicSharedMemorySize,SM_TOTAL);
  dim3 g2(8,Bn);
  qattn_kernel<<<g2,512,SM_TOTAL>>>(V,Out);
}

// round 7
// speedup vs baseline: 1.1614x; 1.0199x over previous
#include <cuda_runtime.h>
#include <cuda_bf16.h>
#include <cstdint>
#define DI __device__ __forceinline__

constexpr int Bn=16, Sn=1024, W=768;
__device__ __align__(128) unsigned short g_A[Bn*Sn*W];
__device__ __align__(128) unsigned short g_B[Bn*Sn*W];

DI unsigned short f2bf(float x){ __nv_bfloat16 h=__float2bfloat16(x); return *(unsigned short*)&h; }

// kernel 1: amplitudes. Row: [c(256)|s(256)|d(256)], d = c-s (A side) or c+s (B side)
__global__ void iqp_amp_kernel(const float* __restrict__ Q, const float* __restrict__ K){
  const int isK=blockIdx.y;
  const float* X = isK?K:Q;
  const int t0 = blockIdx.x*16;
  __shared__ float xs[16][8];
  const int tid=threadIdx.x;
  if(tid<128) xs[tid>>3][tid&7]=X[t0*8+tid];
  __syncthreads();
  const int z=tid;
  unsigned short* G = isK? g_B : g_A;
#pragma unroll 4
  for(int t=0;t<16;++t){
    float sq=0.f,L=0.f;
#pragma unroll
    for(int i=0;i<8;++i){ float xi=xs[t][i]; sq+=xi*xi; L+=((z>>i)&1)?-xi:xi; }
    float ph=-0.5f*L-0.25f*(L*L-sq), s,c; __sincosf(ph,&s,&c);
    size_t base=(size_t)(t0+t)*W;
    G[base+z]=f2bf(c); G[base+256+z]=f2bf(s);
    G[base+512+z]=f2bf(isK? c+s : c-s);
  }
}

// kernel 2: fused fid-attention. i-tile 64 rows, 2 CTAs/SM, 3-stage ring.
constexpr int STG=24576;          // stage: A[64x64]=8192 + B[128x64]=16384
constexpr int SM_RING=0;          // 3 stages = 73728
constexpr int SM_V=73728;         // [1024][8] bf16 = 16384
constexpr int SM_CS=90112;        // [32][8] f32
constexpr int SM_SV=91136;        // [8] f32
constexpr int SM_RED=0;           // reuse ring after loop (4x64x8 f32 = 8KB)
constexpr int SM_TOTAL=91200;

DI uint32_t swz(int r,int c){ return (uint32_t)(r*128 + ((c^(r&7))<<4)); }
DI void cp16(uint32_t d,const void* s){ asm volatile("cp.async.cg.shared.global [%0],[%1],16;\n"::"r"(d),"l"(s):"memory"); }
DI void cpc(){ asm volatile("cp.async.commit_group;\n":::"memory"); }
DI void ldsm_x4(uint32_t* r,uint32_t a){
  asm volatile("ldmatrix.sync.aligned.m8n8.x4.shared.b16 {%0,%1,%2,%3},[%4];\n"
    :"=r"(r[0]),"=r"(r[1]),"=r"(r[2]),"=r"(r[3]):"r"(a));
}
DI void ldsm_x2t(uint32_t* r,uint32_t a){
  asm volatile("ldmatrix.sync.aligned.m8n8.x2.trans.shared.b16 {%0,%1},[%2];\n"
    :"=r"(r[0]),"=r"(r[1]):"r"(a));
}
DI void mma16816(float* c,const uint32_t* a,uint32_t b0,uint32_t b1){
  asm volatile("mma.sync.aligned.m16n8k16.row.col.f32.bf16.bf16.f32 {%0,%1,%2,%3},{%4,%5,%6,%7},{%8,%9},{%0,%1,%2,%3};\n"
    :"+f"(c[0]),"+f"(c[1]),"+f"(c[2]),"+f"(c[3])
    :"r"(a[0]),"r"(a[1]),"r"(a[2]),"r"(a[3]),"r"(b0),"r"(b1));
}
DI uint32_t pack2(float lo,float hi){ uint32_t r; asm("cvt.rn.bf16x2.f32 %0,%1,%2;\n":"=r"(r):"f"(hi),"f"(lo)); return r; }

__global__ __launch_bounds__(256,2)
void qattn_kernel(const float* __restrict__ V, float* __restrict__ Out){
  extern __shared__ char smem[];
  const uint32_t sb=(uint32_t)__cvta_generic_to_shared(smem);
  const int b=blockIdx.y, it=blockIdx.x, tid=threadIdx.x;
  const int lane=tid&31, warp=tid>>5;
  const int wm=warp>>2, wn=warp&3;   // 2M x 4N warps, 32x32 tiles over [64 x 128]

  const unsigned short* gAi = g_A + (size_t)(b*Sn+it*64)*W;
  const unsigned short* gBb = g_B + (size_t)b*Sn*W;

  auto loadChunk=[&](int step){
    int jt=step/12, kc=step-jt*12, st=step%3;
    uint32_t base=sb+SM_RING+st*STG;
    const unsigned short* sA=gAi+kc*64;
#pragma unroll
    for(int m=0;m<2;++m){ int ch=tid+m*256, r=ch>>3, cx=ch&7;
      cp16(base+swz(r,cx), sA+(size_t)r*W+cx*8); }
    const unsigned short* sB=gBb+(size_t)jt*128*W+kc*64;
#pragma unroll
    for(int m=0;m<4;++m){ int ch=tid+m*256, r=ch>>3, cx=ch&7;
      cp16(base+8192+swz(r,cx), sB+(size_t)r*W+cx*8); }
    cpc();
  };
  loadChunk(0); loadChunk(1);

  // V -> bf16 smem + colsum
  const float* gV = V + (size_t)b*Sn*8;
  {
    int e=tid&7, jg=tid>>3; float part=0.f;
#pragma unroll
    for(int k=0;k<32;++k){
      int j=jg+k*32; float v=gV[j*8+e]; part+=v;
      *(unsigned short*)(smem+SM_V+(j*8+e)*2)=f2bf(v);
    }
    *(float*)(smem+SM_CS+(jg*8+e)*4)=part;
  }
  __syncthreads();
  if(tid<8){ float s=0.f; for(int g=0;g<32;++g) s+=*(float*)(smem+SM_CS+(g*8+tid)*4);
             *(float*)(smem+SM_SV+tid*4)=s; }

  float accX[2][4][4], accY[2][4][4], accO[2][4];
#pragma unroll
  for(int m=0;m<2;++m)
#pragma unroll
    for(int n=0;n<4;++n)
#pragma unroll
      for(int x=0;x<4;++x){ accX[m][n][x]=0.f; accY[m][n][x]=0.f; accO[m][x]=0.f; }

  const int lr=lane&15, lch=lane>>4;
  const int brow=(lane&7)+((lane>>4)<<3), bco=(lane>>3)&1;
  const float sc=2.0f/65536.0f;

  for(int jt=0;jt<8;++jt){
#pragma unroll
    for(int kc=0;kc<12;++kc){
      const int c=jt*12+kc;
      if(c+1<96) asm volatile("cp.async.wait_group 1;\n":::"memory");
      else       asm volatile("cp.async.wait_group 0;\n":::"memory");
      __syncthreads();
      if(c+2<96) loadChunk(c+2);     // -> stage (c-1)%3, readers finished pre-sync
      const uint32_t base=sb+SM_RING+(uint32_t)((c%3)*STG);
      const uint32_t at=base, bt=base+8192;
      float (&acc)[2][4][4] = (kc<4)? accX : accY;   // m1->X; m2,m3->Y

#pragma unroll
      for(int k16=0;k16<4;++k16){
        uint32_t aF[2][4], bF[2][4];
        ldsm_x4(aF[0], at+swz(wm*32+lr,    k16*2+lch));
        ldsm_x4(aF[1], at+swz(wm*32+16+lr, k16*2+lch));
        ldsm_x4(bF[0], bt+swz(wn*32+brow,    k16*2+bco));
        ldsm_x4(bF[1], bt+swz(wn*32+16+brow, k16*2+bco));
#pragma unroll
        for(int m=0;m<2;++m)
#pragma unroll
          for(int nf=0;nf<4;++nf)
            mma16816(acc[m][nf], aF[m], bF[nf>>1][(nf&1)*2], bF[nf>>1][(nf&1)*2+1]);
      }

      if(kc==7){   // butterfly: X=m1+m2=re, Y=m2-m1 (m3 adds on top -> im)
#pragma unroll
        for(int m=0;m<2;++m)
#pragma unroll
          for(int n=0;n<4;++n)
#pragma unroll
            for(int x=0;x<4;++x){
              float a=accX[m][n][x], y=accY[m][n][x];
              accX[m][n][x]=a+y; accY[m][n][x]=y-a;
            }
      }

      if(kc==11){  // P = 2*fid -> bf16 A-frags -> P@V
        uint32_t vf[2][2];
#pragma unroll
        for(int q=0;q<2;++q)
          ldsm_x2t(vf[q], sb+SM_V+(uint32_t)((jt*128+wn*32+q*16+(lane&15))*16));
#pragma unroll
        for(int m=0;m<2;++m)
#pragma unroll
          for(int q=0;q<2;++q){
            const int n0=2*q, n1=2*q+1;
            float p[8];
#pragma unroll
            for(int x=0;x<4;++x){
              p[x]  =(accX[m][n0][x]*accX[m][n0][x]+accY[m][n0][x]*accY[m][n0][x])*sc;
              p[4+x]=(accX[m][n1][x]*accX[m][n1][x]+accY[m][n1][x]*accY[m][n1][x])*sc;
            }
            uint32_t pa[4]={pack2(p[0],p[1]),pack2(p[2],p[3]),pack2(p[4],p[5]),pack2(p[6],p[7])};
            mma16816(accO[m], pa, vf[q][0], vf[q][1]);
          }
#pragma unroll
        for(int m=0;m<2;++m)
#pragma unroll
          for(int n=0;n<4;++n)
#pragma unroll
            for(int x=0;x<4;++x){ accX[m][n][x]=0.f; accY[m][n][x]=0.f; }
      }
    }
  }

  __syncthreads();
  // reduce 4 warpN partials, subtract colsum(V), store (64 rows x 8)
  {
    float* red=(float*)(smem+SM_RED)+wn*512;
    const int g=lane>>2, e0=(lane&3)*2;
#pragma unroll
    for(int m=0;m<2;++m){
      int r0=wm*32+m*16+g;
      red[r0*8+e0]=accO[m][0];     red[r0*8+e0+1]=accO[m][1];
      red[(r0+8)*8+e0]=accO[m][2]; red[(r0+8)*8+e0+1]=accO[m][3];
    }
  }
  __syncthreads();
  const float* redall=(const float*)(smem+SM_RED);
  size_t ob=(size_t)(b*Sn+it*64)*8;
#pragma unroll
  for(int rep=0;rep<2;++rep){
    int idx=tid+rep*256, e=idx&7;
    float v=redall[idx]+redall[512+idx]+redall[1024+idx]+redall[1536+idx]
           -*(const float*)(smem+SM_SV+e*4);
    Out[ob+idx]=v;
  }
}

extern "C" void kernel_launch(void* const* d_in,const int* in_sizes,int n_in,void* d_out,int out_size){
  (void)in_sizes;(void)n_in;(void)out_size;
  const float* Q=(const float*)d_in[0];
  const float* K=(const float*)d_in[1];
  const float* V=(const float*)d_in[2];
  float* Out=(float*)d_out;
  dim3 g1(Bn*Sn/16,2);
  iqp_amp_kernel<<<g1,256>>>(Q,K);
  cudaFuncSetAttribute(qattn_kernel,cudaFuncAttributeMaxDynamicSharedMemorySize,SM_TOTAL);
  dim3 g2(16,Bn);
  qattn_kernel<<<g2,256,SM_TOTAL>>>(V,Out);
}